// round 1
// baseline (speedup 1.0000x reference)
#include <cuda_runtime.h>
#include <cuda_bf16.h>
#include <cstdint>

using bf16 = __nv_bfloat16;

// Problem dims (compile-time)
constexpr int BATCH    = 8192;
constexpr int IN_SIZE  = 4096;
constexpr int HIDDEN   = 4096;
constexpr int OUT_SIZE = 1024;

// GEMM tiling
constexpr int BK = 32;
constexpr int STAGES = 3;
constexpr int ROW_ELEMS  = 40;               // 32 data + 8 pad bf16 (80B stride, conflict-free ldmatrix)
constexpr int TILE_ELEMS = 128 * ROW_ELEMS;  // 5120 bf16 per tile
constexpr int STAGE_ELEMS = 3 * TILE_ELEMS;  // Ahi, Alo, B
constexpr int SMEM_BYTES = STAGES * STAGE_ELEMS * 2;  // 92160 B

// ---------------- static device scratch (allocation-free) ----------------
__device__ bf16 g_w1s[HIDDEN * IN_SIZE];
__device__ bf16 g_w2s[HIDDEN * HIDDEN];
__device__ bf16 g_w3s[OUT_SIZE * HIDDEN];
__device__ bf16 g_ahi[BATCH * IN_SIZE];
__device__ bf16 g_alo[BATCH * IN_SIZE];
__device__ bf16 g_bhi[BATCH * HIDDEN];
__device__ bf16 g_blo[BATCH * HIDDEN];
__device__ float g_part[3 * 2048];
__device__ float g_sum[3];

// ---------------- PTX helpers ----------------
__device__ __forceinline__ uint32_t sptr(const void* p) {
    return (uint32_t)__cvta_generic_to_shared(p);
}
__device__ __forceinline__ void cp16(const bf16* dst_smem, const bf16* src_gmem) {
    uint32_t d = sptr(dst_smem);
    asm volatile("cp.async.cg.shared.global [%0], [%1], 16;\n" :: "r"(d), "l"(src_gmem));
}
__device__ __forceinline__ void ldsm4(uint32_t* r, uint32_t addr) {
    asm volatile("ldmatrix.sync.aligned.m8n8.x4.shared.b16 {%0,%1,%2,%3}, [%4];"
                 : "=r"(r[0]), "=r"(r[1]), "=r"(r[2]), "=r"(r[3]) : "r"(addr));
}
__device__ __forceinline__ void mma_bf16(float* d, const uint32_t* a, const uint32_t* b) {
    asm volatile(
        "mma.sync.aligned.m16n8k16.row.col.f32.bf16.bf16.f32 "
        "{%0,%1,%2,%3}, {%4,%5,%6,%7}, {%8,%9}, {%0,%1,%2,%3};"
        : "+f"(d[0]), "+f"(d[1]), "+f"(d[2]), "+f"(d[3])
        : "r"(a[0]), "r"(a[1]), "r"(a[2]), "r"(a[3]), "r"(b[0]), "r"(b[1]));
}

// ---------------- prep kernels ----------------
// sign(w) -> bf16 (+-1 exact), plus deterministic block-partial sum of |w|
__global__ void sign_reduce_kernel(const float4* __restrict__ w4,
                                   __nv_bfloat162* __restrict__ ws2,
                                   int n4, int layer) {
    float s = 0.f;
    for (int i = blockIdx.x * blockDim.x + threadIdx.x; i < n4; i += gridDim.x * blockDim.x) {
        float4 v = w4[i];
        s += fabsf(v.x) + fabsf(v.y) + fabsf(v.z) + fabsf(v.w);
        bf16 s0 = __float2bfloat16((v.x > 0.f) ? 1.f : ((v.x < 0.f) ? -1.f : 0.f));
        bf16 s1 = __float2bfloat16((v.y > 0.f) ? 1.f : ((v.y < 0.f) ? -1.f : 0.f));
        bf16 s2 = __float2bfloat16((v.z > 0.f) ? 1.f : ((v.z < 0.f) ? -1.f : 0.f));
        bf16 s3 = __float2bfloat16((v.w > 0.f) ? 1.f : ((v.w < 0.f) ? -1.f : 0.f));
        ws2[2 * i]     = __halves2bfloat162(s0, s1);
        ws2[2 * i + 1] = __halves2bfloat162(s2, s3);
    }
    __shared__ float red[256];
    red[threadIdx.x] = s;
    __syncthreads();
    for (int o = 128; o > 0; o >>= 1) {
        if (threadIdx.x < o) red[threadIdx.x] += red[threadIdx.x + o];
        __syncthreads();
    }
    if (threadIdx.x == 0) g_part[layer * 2048 + blockIdx.x] = red[0];
}

__global__ void finalize_sum_kernel() {
    __shared__ float red[1024];
    int l = blockIdx.x, t = threadIdx.x;
    red[t] = g_part[l * 2048 + t] + g_part[l * 2048 + 1024 + t];
    __syncthreads();
    for (int o = 512; o > 0; o >>= 1) {
        if (t < o) red[t] += red[t + o];
        __syncthreads();
    }
    if (t == 0) g_sum[l] = red[0];
}

// f32 x -> (hi, lo) bf16 split
__global__ void split_kernel(const float4* __restrict__ x4,
                             __nv_bfloat162* __restrict__ hi2,
                             __nv_bfloat162* __restrict__ lo2, int n4) {
    for (int i = blockIdx.x * blockDim.x + threadIdx.x; i < n4; i += gridDim.x * blockDim.x) {
        float4 v = x4[i];
        bf16 h0 = __float2bfloat16(v.x), h1 = __float2bfloat16(v.y);
        bf16 h2 = __float2bfloat16(v.z), h3 = __float2bfloat16(v.w);
        bf16 l0 = __float2bfloat16(v.x - __bfloat162float(h0));
        bf16 l1 = __float2bfloat16(v.y - __bfloat162float(h1));
        bf16 l2 = __float2bfloat16(v.z - __bfloat162float(h2));
        bf16 l3 = __float2bfloat16(v.w - __bfloat162float(h3));
        hi2[2 * i]     = __halves2bfloat162(h0, h1);
        hi2[2 * i + 1] = __halves2bfloat162(h2, h3);
        lo2[2 * i]     = __halves2bfloat162(l0, l1);
        lo2[2 * i + 1] = __halves2bfloat162(l2, l3);
    }
}

// ---------------- fused binarized GEMM ----------------
// Y[M,N] = alpha * ((Ahi+Alo)[M,K] @ S[N,K]^T) + bias
// EPI==0: relu then re-split to (oHi, oLo) bf16.  EPI==1: sigmoid to oF (f32).
template <int EPI>
__global__ void __launch_bounds__(256, 1) gemm_bwn(
    const bf16* __restrict__ Ahi, const bf16* __restrict__ Alo,
    const bf16* __restrict__ Bs,
    const float* __restrict__ bias, const float* __restrict__ sumAbs, float invCnt,
    int K, int N,
    bf16* __restrict__ oHi, bf16* __restrict__ oLo, float* __restrict__ oF) {
    extern __shared__ bf16 smem[];
    const int tid  = threadIdx.x;
    const int lane = tid & 31;
    const int warp = tid >> 5;
    const int wm = warp & 3;   // 4 warps along M (32 rows each)
    const int wn = warp >> 2;  // 2 warps along N (64 cols each)
    const int bm = blockIdx.y, bn = blockIdx.x;
    const int KT = K / BK;

    const bf16* gAhi = Ahi + (size_t)bm * 128 * K;
    const bf16* gAlo = Alo + (size_t)bm * 128 * K;
    const bf16* gB   = Bs  + (size_t)bn * 128 * K;

    const int lrow = tid >> 2;        // 0..63, second chunk adds 64
    const int lcol = (tid & 3) * 8;   // bf16 elems, 16B chunks

    auto issue = [&](int kt, int stage) {
        bf16* s = smem + stage * STAGE_ELEMS;
        const int kof = kt * BK;
        // A hi
        cp16(s + lrow * ROW_ELEMS + lcol,        gAhi + (size_t)lrow * K + kof + lcol);
        cp16(s + (lrow + 64) * ROW_ELEMS + lcol, gAhi + (size_t)(lrow + 64) * K + kof + lcol);
        // A lo
        bf16* sl = s + TILE_ELEMS;
        cp16(sl + lrow * ROW_ELEMS + lcol,        gAlo + (size_t)lrow * K + kof + lcol);
        cp16(sl + (lrow + 64) * ROW_ELEMS + lcol, gAlo + (size_t)(lrow + 64) * K + kof + lcol);
        // B (signs)
        bf16* sb = s + 2 * TILE_ELEMS;
        cp16(sb + lrow * ROW_ELEMS + lcol,        gB + (size_t)lrow * K + kof + lcol);
        cp16(sb + (lrow + 64) * ROW_ELEMS + lcol, gB + (size_t)(lrow + 64) * K + kof + lcol);
    };

    float acc[2][8][4];
#pragma unroll
    for (int i = 0; i < 2; i++)
#pragma unroll
        for (int j = 0; j < 8; j++)
#pragma unroll
            for (int v = 0; v < 4; v++) acc[i][j][v] = 0.f;

    auto compute = [&](int stage) {
        const bf16* sA  = smem + stage * STAGE_ELEMS;
        const bf16* sAl = sA + TILE_ELEMS;
        const bf16* sB  = sA + 2 * TILE_ELEMS;
#pragma unroll
        for (int ks = 0; ks < 2; ks++) {
            uint32_t ah[2][4], al[2][4], bb[8][2];
#pragma unroll
            for (int i = 0; i < 2; i++) {
                int r = wm * 32 + i * 16 + (lane & 15);
                int c = ks * 16 + (lane >> 4) * 8;
                ldsm4(ah[i], sptr(sA  + r * ROW_ELEMS + c));
                ldsm4(al[i], sptr(sAl + r * ROW_ELEMS + c));
            }
#pragma unroll
            for (int jj = 0; jj < 4; jj++) {
                int n = wn * 64 + jj * 16 + ((lane >> 4) & 1) * 8 + (lane & 7);
                int c = ks * 16 + ((lane >> 3) & 1) * 8;
                uint32_t r[4];
                ldsm4(r, sptr(sB + n * ROW_ELEMS + c));
                bb[2 * jj][0] = r[0]; bb[2 * jj][1] = r[1];
                bb[2 * jj + 1][0] = r[2]; bb[2 * jj + 1][1] = r[3];
            }
#pragma unroll
            for (int i = 0; i < 2; i++)
#pragma unroll
                for (int j = 0; j < 8; j++) {
                    mma_bf16(acc[i][j], ah[i], bb[j]);
                    mma_bf16(acc[i][j], al[i], bb[j]);
                }
        }
    };

    // prologue: stages 0,1
    issue(0, 0);
    asm volatile("cp.async.commit_group;" ::: "memory");
    issue(1, 1);
    asm volatile("cp.async.commit_group;" ::: "memory");

    for (int kt = 0; kt < KT; kt++) {
        asm volatile("cp.async.wait_group 1;" ::: "memory");
        __syncthreads();
        int kn = kt + 2;
        if (kn < KT) issue(kn, kn % STAGES);
        asm volatile("cp.async.commit_group;" ::: "memory");  // empty groups keep count uniform
        compute(kt % STAGES);
    }

    // ---------------- epilogue ----------------
    const float alpha = __ldg(sumAbs) * invCnt;
    const int r0 = bm * 128 + wm * 32 + (lane >> 2);
    const int c0 = bn * 128 + wn * 64 + (lane & 3) * 2;
#pragma unroll
    for (int i = 0; i < 2; i++) {
#pragma unroll
        for (int j = 0; j < 8; j++) {
            int row = r0 + i * 16;
            int col = c0 + j * 8;
            float bx = __ldg(bias + col), by = __ldg(bias + col + 1);
            float v00 = acc[i][j][0] * alpha + bx;
            float v01 = acc[i][j][1] * alpha + by;
            float v10 = acc[i][j][2] * alpha + bx;
            float v11 = acc[i][j][3] * alpha + by;
            if (EPI == 0) {
                v00 = fmaxf(v00, 0.f); v01 = fmaxf(v01, 0.f);
                v10 = fmaxf(v10, 0.f); v11 = fmaxf(v11, 0.f);
                // re-split for next layer
                bf16 h00 = __float2bfloat16(v00), h01 = __float2bfloat16(v01);
                bf16 h10 = __float2bfloat16(v10), h11 = __float2bfloat16(v11);
                bf16 l00 = __float2bfloat16(v00 - __bfloat162float(h00));
                bf16 l01 = __float2bfloat16(v01 - __bfloat162float(h01));
                bf16 l10 = __float2bfloat16(v10 - __bfloat162float(h10));
                bf16 l11 = __float2bfloat16(v11 - __bfloat162float(h11));
                size_t i0 = (size_t)row * N + col;
                size_t i1 = (size_t)(row + 8) * N + col;
                *reinterpret_cast<__nv_bfloat162*>(oHi + i0) = __halves2bfloat162(h00, h01);
                *reinterpret_cast<__nv_bfloat162*>(oHi + i1) = __halves2bfloat162(h10, h11);
                *reinterpret_cast<__nv_bfloat162*>(oLo + i0) = __halves2bfloat162(l00, l01);
                *reinterpret_cast<__nv_bfloat162*>(oLo + i1) = __halves2bfloat162(l10, l11);
            } else {
                float2 s0, s1;
                s0.x = 1.f / (1.f + __expf(-v00));
                s0.y = 1.f / (1.f + __expf(-v01));
                s1.x = 1.f / (1.f + __expf(-v10));
                s1.y = 1.f / (1.f + __expf(-v11));
                *reinterpret_cast<float2*>(oF + (size_t)row * N + col)       = s0;
                *reinterpret_cast<float2*>(oF + (size_t)(row + 8) * N + col) = s1;
            }
        }
    }
}

// ---------------- host launch ----------------
extern "C" void kernel_launch(void* const* d_in, const int* in_sizes, int n_in,
                              void* d_out, int out_size) {
    const float* x  = (const float*)d_in[0];
    const float* w1 = (const float*)d_in[1];
    const float* b1 = (const float*)d_in[2];
    const float* w2 = (const float*)d_in[3];
    const float* b2 = (const float*)d_in[4];
    const float* w3 = (const float*)d_in[5];
    const float* b3 = (const float*)d_in[6];

    void *pw1, *pw2, *pw3, *pahi, *palo, *pbhi, *pblo, *psum;
    cudaGetSymbolAddress(&pw1, g_w1s);
    cudaGetSymbolAddress(&pw2, g_w2s);
    cudaGetSymbolAddress(&pw3, g_w3s);
    cudaGetSymbolAddress(&pahi, g_ahi);
    cudaGetSymbolAddress(&palo, g_alo);
    cudaGetSymbolAddress(&pbhi, g_bhi);
    cudaGetSymbolAddress(&pblo, g_blo);
    cudaGetSymbolAddress(&psum, g_sum);
    float* sum = (float*)psum;

    // 1. binarize weights + |w| partial sums (deterministic)
    sign_reduce_kernel<<<2048, 256>>>((const float4*)w1, (__nv_bfloat162*)pw1,
                                      HIDDEN * IN_SIZE / 4, 0);
    sign_reduce_kernel<<<2048, 256>>>((const float4*)w2, (__nv_bfloat162*)pw2,
                                      HIDDEN * HIDDEN / 4, 1);
    sign_reduce_kernel<<<2048, 256>>>((const float4*)w3, (__nv_bfloat162*)pw3,
                                      OUT_SIZE * HIDDEN / 4, 2);
    finalize_sum_kernel<<<3, 1024>>>();

    // 2. split x into hi/lo bf16
    split_kernel<<<2048, 256>>>((const float4*)x, (__nv_bfloat162*)pahi,
                                (__nv_bfloat162*)palo, BATCH * IN_SIZE / 4);

    // 3. three GEMMs
    cudaFuncSetAttribute(gemm_bwn<0>, cudaFuncAttributeMaxDynamicSharedMemorySize, SMEM_BYTES);
    cudaFuncSetAttribute(gemm_bwn<1>, cudaFuncAttributeMaxDynamicSharedMemorySize, SMEM_BYTES);

    gemm_bwn<0><<<dim3(HIDDEN / 128, BATCH / 128), 256, SMEM_BYTES>>>(
        (const bf16*)pahi, (const bf16*)palo, (const bf16*)pw1,
        b1, sum + 0, 1.0f / ((float)HIDDEN * (float)IN_SIZE),
        IN_SIZE, HIDDEN, (bf16*)pbhi, (bf16*)pblo, nullptr);

    gemm_bwn<0><<<dim3(HIDDEN / 128, BATCH / 128), 256, SMEM_BYTES>>>(
        (const bf16*)pbhi, (const bf16*)pblo, (const bf16*)pw2,
        b2, sum + 1, 1.0f / ((float)HIDDEN * (float)HIDDEN),
        HIDDEN, HIDDEN, (bf16*)pahi, (bf16*)palo, nullptr);

    gemm_bwn<1><<<dim3(OUT_SIZE / 128, BATCH / 128), 256, SMEM_BYTES>>>(
        (const bf16*)pahi, (const bf16*)palo, (const bf16*)pw3,
        b3, sum + 2, 1.0f / ((float)OUT_SIZE * (float)HIDDEN),
        HIDDEN, OUT_SIZE, nullptr, nullptr, (float*)d_out);
}